// round 12
// baseline (speedup 1.0000x reference)
#include <cuda_runtime.h>
#include <cuda_bf16.h>
#include <cstdint>

#define BATCH 8192
#define INDIM 1024
#define LAT   16384
#define TOPK  64
#define CAND  96
#define MAXC  128
#define EQCAP 128

// GEMM tiling (HMMA mma.sync m16n8k16 bf16): 128x128 CTA tile, 8 warps (2x4) of 64x32
#define GM 128
#define GN 128
#define GK 64
#define NCHT (INDIM/GK)        /* 16 */
#define GST 3
#define GSTB ((GM+GN)*GK*2)    /* 32768: A 16KB + B 16KB */
#define SMEM_GEMM (GST*GSTB)   /* 98304 */

// ---------- static scratch ----------
__device__ __align__(16) __nv_bfloat16 g_Xb[(size_t)BATCH*INDIM];
__device__ __align__(16) __nv_bfloat16 g_Wb[(size_t)LAT*INDIM];
__device__ __align__(16) __nv_bfloat16 g_zb[(size_t)BATCH*LAT];
__device__ __align__(16) float g_WdT[(size_t)LAT*INDIM];
__device__ __align__(16) float g_cval[(size_t)BATCH*MAXC];
__device__ int   g_cidx[(size_t)BATCH*MAXC];
__device__ int   g_ccnt[BATCH];
__device__ __align__(16) float g_aval[(size_t)BATCH*TOPK];
__device__ int   g_aidx[(size_t)BATCH*TOPK];

// ---------- helpers ----------
__device__ __forceinline__ uint32_t s2u(const void* p){
    uint32_t a;
    asm("{ .reg .u64 t; cvta.to.shared.u64 t, %1; cvt.u32.u64 %0, t; }" : "=r"(a) : "l"(p));
    return a;
}
__device__ __forceinline__ uint32_t swz(uint32_t x){ return x ^ ((x>>3)&0x70); }
__device__ __forceinline__ void cp16(uint32_t d, const void* s){
    asm volatile("cp.async.cg.shared.global [%0], [%1], 16;" :: "r"(d), "l"(s));
}
#define CPCOMMIT asm volatile("cp.async.commit_group;" ::: "memory")
#define CPWAIT1  asm volatile("cp.async.wait_group 1;" ::: "memory")
#define CPWAIT0  asm volatile("cp.async.wait_group 0;" ::: "memory")

__device__ __forceinline__ void ldsm4(uint32_t& r0, uint32_t& r1, uint32_t& r2, uint32_t& r3, uint32_t a){
    asm volatile("ldmatrix.sync.aligned.m8n8.x4.shared.b16 {%0,%1,%2,%3}, [%4];"
                 : "=r"(r0), "=r"(r1), "=r"(r2), "=r"(r3) : "r"(a));
}
__device__ __forceinline__ void mma16816(float* d, const uint32_t* a, uint32_t b0, uint32_t b1){
    asm volatile("mma.sync.aligned.m16n8k16.row.col.f32.bf16.bf16.f32 "
                 "{%0,%1,%2,%3}, {%4,%5,%6,%7}, {%8,%9}, {%0,%1,%2,%3};"
                 : "+f"(d[0]), "+f"(d[1]), "+f"(d[2]), "+f"(d[3])
                 : "r"(a[0]), "r"(a[1]), "r"(a[2]), "r"(a[3]), "r"(b0), "r"(b1));
}

// ---------- conversion / transpose ----------
__global__ void k_cvtx(const float4* __restrict__ s, __nv_bfloat162* __restrict__ d, int n4){
    int i = blockIdx.x*256 + threadIdx.x;
    if (i < n4){
        float4 v = s[i];
        d[2*i]   = __floats2bfloat162_rn(v.x, v.y);
        d[2*i+1] = __floats2bfloat162_rn(v.z, v.w);
    }
}
__global__ void k_transp(const float* __restrict__ Wd){
    __shared__ float tile[32][33];
    int l0 = blockIdx.x*32, d0 = blockIdx.y*32;
    int tx = threadIdx.x, ty = threadIdx.y;
    #pragma unroll
    for (int i=0;i<32;i+=8) tile[ty+i][tx] = Wd[(size_t)(d0+ty+i)*LAT + l0+tx];
    __syncthreads();
    #pragma unroll
    for (int i=0;i<32;i+=8) g_WdT[(size_t)(l0+ty+i)*INDIM + d0+tx] = tile[tx][ty+i];
}

// ---------- bf16 GEMM: z_approx = relu(X @ Wenc^T + b) -> bf16 ----------
__device__ __forceinline__ void g_load(int c, uint32_t sb, int t,
                                       const __nv_bfloat16* Ap, const __nv_bfloat16* Bp){
    uint32_t st = sb + (uint32_t)(c % GST)*GSTB;
    #pragma unroll
    for (int i=0;i<8;i++){
        int id = t + i*256;
        if (id < 1024){
            int r = id>>3, q = id&7;
            cp16(st + swz((r<<7)|(q<<4)), Ap + (size_t)r*INDIM + c*GK + q*8);
        } else {
            int j = id - 1024; int r = j>>3, q = j&7;
            cp16(st + 16384 + swz((r<<7)|(q<<4)), Bp + (size_t)r*INDIM + c*GK + q*8);
        }
    }
    CPCOMMIT;
}

__global__ void __launch_bounds__(256,2) k_gemm(const float* __restrict__ benc){
    extern __shared__ __align__(1024) char smraw[];
    uint32_t sb = s2u(smraw);
    int t = threadIdx.x, lane = t&31, w = t>>5;
    int wm = w>>2, wn = w&3;
    int m0 = blockIdx.x*GM, n0 = blockIdx.y*GN;
    const __nv_bfloat16* Ap = g_Xb + (size_t)m0*INDIM;
    const __nv_bfloat16* Bp = g_Wb + (size_t)n0*INDIM;

    float acc[4][4][4];
    #pragma unroll
    for (int mt=0;mt<4;mt++)
        #pragma unroll
        for (int nt=0;nt<4;nt++)
            #pragma unroll
            for (int k=0;k<4;k++) acc[mt][nt][k]=0.f;

    g_load(0, sb, t, Ap, Bp);
    g_load(1, sb, t, Ap, Bp);

    for (int c=0;c<NCHT;c++){
        if (c == NCHT-1) { CPWAIT0; } else { CPWAIT1; }
        __syncthreads();
        // Single barrier per chunk: passing it proves every thread finished
        // compute of chunk c-1, so overwriting stage (c+2)%3 == (c-1)%3 is safe.
        if (c+2 < NCHT) g_load(c+2, sb, t, Ap, Bp);

        uint32_t st = sb + (uint32_t)(c % GST)*GSTB;
        uint32_t ab = st, bb = st + 16384;
        #pragma unroll
        for (int kk=0;kk<4;kk++){
            uint32_t afr[4][4];
            #pragma unroll
            for (int mt=0;mt<4;mt++){
                int row = wm*64 + mt*16 + (lane&15);
                ldsm4(afr[mt][0],afr[mt][1],afr[mt][2],afr[mt][3],
                      ab + swz((uint32_t)(row*128 + kk*32 + ((lane>>4)<<4))));
            }
            uint32_t bfr[2][4];
            #pragma unroll
            for (int np=0;np<2;np++){
                int rown = wn*32 + np*16 + ((lane>>4)&1)*8 + (lane&7);
                ldsm4(bfr[np][0],bfr[np][1],bfr[np][2],bfr[np][3],
                      bb + swz((uint32_t)(rown*128 + kk*32 + (((lane>>3)&1)<<4))));
            }
            #pragma unroll
            for (int mt=0;mt<4;mt++)
                #pragma unroll
                for (int nt=0;nt<4;nt++)
                    mma16816(acc[mt][nt], afr[mt], bfr[nt>>1][(nt&1)*2], bfr[nt>>1][(nt&1)*2+1]);
        }
    }

    float bb2[4][2];
    #pragma unroll
    for (int nt=0;nt<4;nt++){
        int cc = n0 + wn*32 + nt*8 + (lane&3)*2;
        bb2[nt][0] = __ldg(&benc[cc]);
        bb2[nt][1] = __ldg(&benc[cc+1]);
    }
    #pragma unroll
    for (int mt=0;mt<4;mt++){
        int r0 = m0 + wm*64 + mt*16 + (lane>>2);
        #pragma unroll
        for (int nt=0;nt<4;nt++){
            int cc = n0 + wn*32 + nt*8 + (lane&3)*2;
            float v0 = fmaxf(acc[mt][nt][0] + bb2[nt][0], 0.f);
            float v1 = fmaxf(acc[mt][nt][1] + bb2[nt][1], 0.f);
            float v2 = fmaxf(acc[mt][nt][2] + bb2[nt][0], 0.f);
            float v3 = fmaxf(acc[mt][nt][3] + bb2[nt][1], 0.f);
            *(__nv_bfloat162*)&g_zb[(size_t)r0*LAT + cc]     = __floats2bfloat162_rn(v0, v1);
            *(__nv_bfloat162*)&g_zb[(size_t)(r0+8)*LAT + cc] = __floats2bfloat162_rn(v2, v3);
        }
    }
}

// ---------- candidate selection: conflict-free scans, fused collect ----------
__global__ void __launch_bounds__(256,1) k_cand(){
    __shared__ uint16_t keys[LAT];
    __shared__ int hist[256];
    __shared__ int misc[2];
    __shared__ int cnt, eqcnt;
    __shared__ int eqbuf[EQCAP];
    int row = blockIdx.x, t = threadIdx.x;

    const uint4* src = (const uint4*)(g_zb + (size_t)row*LAT);
    uint4* dk = (uint4*)keys;
    for (int i=t;i<LAT/8;i+=256) dk[i] = src[i];
    __syncthreads();

    const uint32_t* kw = (const uint32_t*)keys;   // 8192 words, 2 keys each
    int need = CAND;
    // pass 1: high byte (zeros skipped: output-neutral)
    hist[t]=0; __syncthreads();
    #pragma unroll 4
    for (int i=0;i<32;i++){
        uint32_t w2 = kw[t + 256*i];
        int k0 = w2 & 0xFFFF, k1 = (int)(w2 >> 16);
        if (k0) atomicAdd(&hist[k0>>8], 1);
        if (k1) atomicAdd(&hist[k1>>8], 1);
    }
    __syncthreads();
    if (t==0){
        int cum=0, b=255;
        for (; b>0; b--){ cum += hist[b]; if (cum>=need) break; }
        if (cum < need) cum += hist[0];
        misc[0]=b; misc[1]=need-(cum-hist[b]);
    }
    __syncthreads();
    int bhi = misc[0]; need = misc[1];
    __syncthreads();
    // pass 2: low byte within bucket
    hist[t]=0; __syncthreads();
    #pragma unroll 4
    for (int i=0;i<32;i++){
        uint32_t w2 = kw[t + 256*i];
        int k0 = w2 & 0xFFFF, k1 = (int)(w2 >> 16);
        if (k0 && (k0>>8)==bhi) atomicAdd(&hist[k0&255], 1);
        if (k1 && (k1>>8)==bhi) atomicAdd(&hist[k1&255], 1);
    }
    __syncthreads();
    if (t==0){
        int cum=0, b=255;
        for (; b>0; b--){ cum += hist[b]; if (cum>=need) break; }
        misc[0]=b; cnt=0; eqcnt=0;
    }
    __syncthreads();
    const int T = (bhi<<8) | misc[0];
    // fused collect: >T to global list, ==T staged to eqbuf
    #pragma unroll 4
    for (int i=0;i<32;i++){
        int wi = t + 256*i;
        uint32_t w2 = kw[wi];
        int k0 = w2 & 0xFFFF, k1 = (int)(w2 >> 16);
        if (k0 > T){
            int p = atomicAdd(&cnt,1);
            if (p < MAXC) g_cidx[(size_t)row*MAXC+p] = 2*wi;
        } else if (k0 == T && T > 0){
            int e = atomicAdd(&eqcnt,1);
            if (e < EQCAP) eqbuf[e] = 2*wi;
        }
        if (k1 > T){
            int p = atomicAdd(&cnt,1);
            if (p < MAXC) g_cidx[(size_t)row*MAXC+p] = 2*wi+1;
        } else if (k1 == T && T > 0){
            int e = atomicAdd(&eqcnt,1);
            if (e < EQCAP) eqbuf[e] = 2*wi+1;
        }
    }
    __syncthreads();
    int gt = (cnt < MAXC) ? cnt : MAXC;
    int ne = eqcnt; if (ne > EQCAP) ne = EQCAP;
    if (t < ne){
        int p = gt + t;
        if (p < MAXC) g_cidx[(size_t)row*MAXC+p] = eqbuf[t];
    }
    __syncthreads();
    if (t==0){
        int tot = gt + ne;
        g_ccnt[row] = (tot < MAXC) ? tot : MAXC;
    }
}

// ---------- exact fp32 recompute (2 candidates per warp) ----------
__global__ void __launch_bounds__(256,1) k_exact(const float* __restrict__ x,
                                                 const float* __restrict__ W,
                                                 const float* __restrict__ benc){
    __shared__ float4 xs[INDIM/4];
    __shared__ int cidx_s[MAXC];
    __shared__ int ccs;
    int row = blockIdx.x, t = threadIdx.x;
    xs[t] = ((const float4*)(x + (size_t)row*INDIM))[t];
    if (t < MAXC) cidx_s[t] = g_cidx[(size_t)row*MAXC+t];
    if (t == 0) ccs = g_ccnt[row];
    __syncthreads();
    int w = t>>5, lane = t&31;
    for (int p = 2*w; p < ccs; p += 16){
        int c1 = p+1;
        bool has1 = (c1 < ccs);
        int i0 = cidx_s[p];
        int i1 = has1 ? cidx_s[c1] : i0;
        const float4* w0 = (const float4*)(W + (size_t)i0*INDIM);
        const float4* w1 = (const float4*)(W + (size_t)i1*INDIM);
        float s0 = 0.f, s1 = 0.f;
        #pragma unroll
        for (int i=0;i<8;i++){
            float4 a = __ldg(&w0[lane + 32*i]);
            float4 b = __ldg(&w1[lane + 32*i]);
            float4 xv = xs[lane + 32*i];
            s0 = fmaf(a.x, xv.x, s0); s0 = fmaf(a.y, xv.y, s0);
            s0 = fmaf(a.z, xv.z, s0); s0 = fmaf(a.w, xv.w, s0);
            s1 = fmaf(b.x, xv.x, s1); s1 = fmaf(b.y, xv.y, s1);
            s1 = fmaf(b.z, xv.z, s1); s1 = fmaf(b.w, xv.w, s1);
        }
        #pragma unroll
        for (int o=16;o;o>>=1){
            s0 += __shfl_xor_sync(0xFFFFFFFFu, s0, o);
            s1 += __shfl_xor_sync(0xFFFFFFFFu, s1, o);
        }
        if (lane==0){
            g_cval[(size_t)row*MAXC+p] = fmaxf(s0 + __ldg(&benc[i0]), 0.f);
            if (has1) g_cval[(size_t)row*MAXC+c1] = fmaxf(s1 + __ldg(&benc[i1]), 0.f);
        }
    }
}

// ---------- fused zero + exact top-64 + full-row write ----------
__global__ void __launch_bounds__(256,1) k_selz(float* __restrict__ zout){
    extern __shared__ __align__(16) float rowbuf[];       // 16384 floats (64KB)
    __shared__ float v[MAXC];
    __shared__ int id[MAXC];
    __shared__ int ccs;
    int row = blockIdx.x, t = threadIdx.x;
    float4* rb4 = (float4*)rowbuf;
    #pragma unroll
    for (int i=t;i<LAT/4;i+=256) rb4[i] = make_float4(0.f,0.f,0.f,0.f);
    if (t==0) ccs = g_ccnt[row];
    if (t < TOPK){ g_aval[(size_t)row*TOPK+t] = 0.f; g_aidx[(size_t)row*TOPK+t] = 0; }
    __syncthreads();
    if (t < ccs){ v[t] = g_cval[(size_t)row*MAXC+t]; id[t] = g_cidx[(size_t)row*MAXC+t]; }
    __syncthreads();
    if (t < ccs){
        float vt = v[t]; int it = id[t];
        int r = 0;
        for (int j=0;j<ccs;j++)
            r += (v[j] > vt) || (v[j] == vt && id[j] < it);
        if (r < TOPK){
            g_aval[(size_t)row*TOPK+r] = vt;
            g_aidx[(size_t)row*TOPK+r] = it;
            rowbuf[it] = vt;
        }
    }
    __syncthreads();
    float4* dst = (float4*)(zout + (size_t)row*LAT);
    #pragma unroll
    for (int i=t;i<LAT/4;i+=256) dst[i] = rb4[i];
}

// ---------- sparse decode ----------
__global__ void __launch_bounds__(256,1) k_decode(const float* __restrict__ bdec,
                                                  float* __restrict__ recon){
    int row = blockIdx.x, t = threadIdx.x;
    __shared__ float sv[TOPK]; __shared__ int si[TOPK];
    if (t < TOPK){ sv[t]=g_aval[(size_t)row*TOPK+t]; si[t]=g_aidx[(size_t)row*TOPK+t]; }
    __syncthreads();
    float a0=bdec[t], a1=bdec[t+256], a2=bdec[t+512], a3=bdec[t+768];
    #pragma unroll 4
    for (int j=0;j<TOPK;j++){
        const float* wr = g_WdT + (size_t)si[j]*INDIM;
        float vv = sv[j];
        a0 = fmaf(vv, __ldg(wr+t),     a0);
        a1 = fmaf(vv, __ldg(wr+t+256), a1);
        a2 = fmaf(vv, __ldg(wr+t+512), a2);
        a3 = fmaf(vv, __ldg(wr+t+768), a3);
    }
    float* r = recon + (size_t)row*INDIM;
    r[t]=a0; r[t+256]=a1; r[t+512]=a2; r[t+768]=a3;
}

extern "C" void kernel_launch(void* const* d_in, const int* in_sizes, int n_in,
                              void* d_out, int out_size){
    const float* x    = (const float*)d_in[0];
    const float* Wenc = (const float*)d_in[1];
    const float* benc = (const float*)d_in[2];
    const float* Wdec = (const float*)d_in[3];
    const float* bdec = (const float*)d_in[4];
    float* out   = (float*)d_out;
    float* recon = out;
    float* zout  = out + (size_t)BATCH*INDIM;

    __nv_bfloat16 *xb, *wb;
    cudaGetSymbolAddress((void**)&xb, g_Xb);
    cudaGetSymbolAddress((void**)&wb, g_Wb);

    cudaFuncSetAttribute(k_gemm, cudaFuncAttributeMaxDynamicSharedMemorySize, SMEM_GEMM);
    cudaFuncSetAttribute(k_selz, cudaFuncAttributeMaxDynamicSharedMemorySize, 65536);

    int n4x = BATCH*INDIM/4, n4w = LAT*INDIM/4;
    // launch order: slot 4 (profiled) = k_gemm (bf16 GEMM never yet measured)
    k_cvtx<<<(n4x+255)/256, 256>>>((const float4*)x, (__nv_bfloat162*)xb, n4x);
    k_cvtx<<<(n4w+255)/256, 256>>>((const float4*)Wenc, (__nv_bfloat162*)wb, n4w);
    k_transp<<<dim3(LAT/32, INDIM/32), dim3(32,8)>>>(Wdec);
    k_gemm<<<dim3(BATCH/GM, LAT/GN), 256, SMEM_GEMM>>>(benc);
    k_cand<<<BATCH, 256>>>();
    k_exact<<<BATCH, 256>>>(x, Wenc, benc);
    k_selz<<<BATCH, 256, 65536>>>(zout);
    k_decode<<<BATCH, 256>>>(bdec, recon);
}

// round 13
// speedup vs baseline: 1.5036x; 1.5036x over previous
#include <cuda_runtime.h>
#include <cuda_bf16.h>
#include <cstdint>

#define BATCH 8192
#define INDIM 1024
#define LAT   16384
#define TOPK  64
#define CAND  96
#define MAXC  128
#define EQCAP 128

// GEMM tiling (HMMA mma.sync m16n8k16 bf16): 128x128 CTA tile, 8 warps (2x4) of 64x32
#define GM 128
#define GN 128
#define GK 64
#define NCHT (INDIM/GK)        /* 16 */
#define GST 3
#define GSTB ((GM+GN)*GK*2)    /* 32768: A 16KB + B 16KB */
#define SMEM_GEMM (GST*GSTB)   /* 98304 */

// ---------- static scratch ----------
__device__ __align__(16) __nv_bfloat16 g_Xb[(size_t)BATCH*INDIM];
__device__ __align__(16) __nv_bfloat16 g_Wb[(size_t)LAT*INDIM];
__device__ __align__(16) __nv_bfloat16 g_zb[(size_t)BATCH*LAT];
__device__ __align__(16) float g_WdT[(size_t)LAT*INDIM];
__device__ __align__(16) float g_cval[(size_t)BATCH*MAXC];
__device__ int   g_cidx[(size_t)BATCH*MAXC];
__device__ int   g_ccnt[BATCH];
__device__ __align__(16) float g_aval[(size_t)BATCH*TOPK];
__device__ int   g_aidx[(size_t)BATCH*TOPK];

// ---------- helpers ----------
__device__ __forceinline__ uint32_t s2u(const void* p){
    uint32_t a;
    asm("{ .reg .u64 t; cvta.to.shared.u64 t, %1; cvt.u32.u64 %0, t; }" : "=r"(a) : "l"(p));
    return a;
}
__device__ __forceinline__ uint32_t swz(uint32_t x){ return x ^ ((x>>3)&0x70); }
__device__ __forceinline__ void cp16(uint32_t d, const void* s){
    asm volatile("cp.async.cg.shared.global [%0], [%1], 16;" :: "r"(d), "l"(s));
}
#define CPCOMMIT asm volatile("cp.async.commit_group;" ::: "memory")
#define CPWAIT1  asm volatile("cp.async.wait_group 1;" ::: "memory")
#define CPWAIT0  asm volatile("cp.async.wait_group 0;" ::: "memory")

__device__ __forceinline__ void ldsm4(uint32_t& r0, uint32_t& r1, uint32_t& r2, uint32_t& r3, uint32_t a){
    asm volatile("ldmatrix.sync.aligned.m8n8.x4.shared.b16 {%0,%1,%2,%3}, [%4];"
                 : "=r"(r0), "=r"(r1), "=r"(r2), "=r"(r3) : "r"(a));
}
__device__ __forceinline__ void mma16816(float* d, const uint32_t* a, uint32_t b0, uint32_t b1){
    asm volatile("mma.sync.aligned.m16n8k16.row.col.f32.bf16.bf16.f32 "
                 "{%0,%1,%2,%3}, {%4,%5,%6,%7}, {%8,%9}, {%0,%1,%2,%3};"
                 : "+f"(d[0]), "+f"(d[1]), "+f"(d[2]), "+f"(d[3])
                 : "r"(a[0]), "r"(a[1]), "r"(a[2]), "r"(a[3]), "r"(b0), "r"(b1));
}

// ---------- conversion / transpose ----------
__global__ void k_cvtx(const float4* __restrict__ s, __nv_bfloat162* __restrict__ d, int n4){
    int i = blockIdx.x*256 + threadIdx.x;
    if (i < n4){
        float4 v = s[i];
        d[2*i]   = __floats2bfloat162_rn(v.x, v.y);
        d[2*i+1] = __floats2bfloat162_rn(v.z, v.w);
    }
}
__global__ void k_transp(const float* __restrict__ Wd){
    __shared__ float tile[32][33];
    int l0 = blockIdx.x*32, d0 = blockIdx.y*32;
    int tx = threadIdx.x, ty = threadIdx.y;
    #pragma unroll
    for (int i=0;i<32;i+=8) tile[ty+i][tx] = Wd[(size_t)(d0+ty+i)*LAT + l0+tx];
    __syncthreads();
    #pragma unroll
    for (int i=0;i<32;i+=8) g_WdT[(size_t)(l0+ty+i)*INDIM + d0+tx] = tile[tx][ty+i];
}

// ---------- bf16 GEMM: z_approx = relu(X @ Wenc^T + b) -> bf16 ----------
__device__ __forceinline__ void g_load(int c, uint32_t sb, int t,
                                       const __nv_bfloat16* Ap, const __nv_bfloat16* Bp){
    uint32_t st = sb + (uint32_t)(c % GST)*GSTB;
    #pragma unroll
    for (int i=0;i<8;i++){
        int id = t + i*256;
        if (id < 1024){
            int r = id>>3, q = id&7;
            cp16(st + swz((r<<7)|(q<<4)), Ap + (size_t)r*INDIM + c*GK + q*8);
        } else {
            int j = id - 1024; int r = j>>3, q = j&7;
            cp16(st + 16384 + swz((r<<7)|(q<<4)), Bp + (size_t)r*INDIM + c*GK + q*8);
        }
    }
    CPCOMMIT;
}

__global__ void __launch_bounds__(256,2) k_gemm(const float* __restrict__ benc){
    extern __shared__ __align__(1024) char smraw[];
    uint32_t sb = s2u(smraw);
    int t = threadIdx.x, lane = t&31, w = t>>5;
    int wm = w>>2, wn = w&3;
    int m0 = blockIdx.x*GM, n0 = blockIdx.y*GN;
    const __nv_bfloat16* Ap = g_Xb + (size_t)m0*INDIM;
    const __nv_bfloat16* Bp = g_Wb + (size_t)n0*INDIM;

    float acc[4][4][4];
    #pragma unroll
    for (int mt=0;mt<4;mt++)
        #pragma unroll
        for (int nt=0;nt<4;nt++)
            #pragma unroll
            for (int k=0;k<4;k++) acc[mt][nt][k]=0.f;

    g_load(0, sb, t, Ap, Bp);
    g_load(1, sb, t, Ap, Bp);

    for (int c=0;c<NCHT;c++){
        if (c == NCHT-1) { CPWAIT0; } else { CPWAIT1; }
        __syncthreads();
        if (c+2 < NCHT) g_load(c+2, sb, t, Ap, Bp);

        uint32_t st = sb + (uint32_t)(c % GST)*GSTB;
        uint32_t ab = st, bb = st + 16384;
        #pragma unroll
        for (int kk=0;kk<4;kk++){
            uint32_t afr[4][4];
            #pragma unroll
            for (int mt=0;mt<4;mt++){
                int row = wm*64 + mt*16 + (lane&15);
                ldsm4(afr[mt][0],afr[mt][1],afr[mt][2],afr[mt][3],
                      ab + swz((uint32_t)(row*128 + kk*32 + ((lane>>4)<<4))));
            }
            uint32_t bfr[2][4];
            #pragma unroll
            for (int np=0;np<2;np++){
                int rown = wn*32 + np*16 + ((lane>>4)&1)*8 + (lane&7);
                ldsm4(bfr[np][0],bfr[np][1],bfr[np][2],bfr[np][3],
                      bb + swz((uint32_t)(rown*128 + kk*32 + (((lane>>3)&1)<<4))));
            }
            #pragma unroll
            for (int mt=0;mt<4;mt++)
                #pragma unroll
                for (int nt=0;nt<4;nt++)
                    mma16816(acc[mt][nt], afr[mt], bfr[nt>>1][(nt&1)*2], bfr[nt>>1][(nt&1)*2+1]);
        }
        __syncthreads();   // phase-lock barrier: measured ~2x GEMM slowdown when removed (R12)
    }

    float bb2[4][2];
    #pragma unroll
    for (int nt=0;nt<4;nt++){
        int cc = n0 + wn*32 + nt*8 + (lane&3)*2;
        bb2[nt][0] = __ldg(&benc[cc]);
        bb2[nt][1] = __ldg(&benc[cc+1]);
    }
    #pragma unroll
    for (int mt=0;mt<4;mt++){
        int r0 = m0 + wm*64 + mt*16 + (lane>>2);
        #pragma unroll
        for (int nt=0;nt<4;nt++){
            int cc = n0 + wn*32 + nt*8 + (lane&3)*2;
            float v0 = fmaxf(acc[mt][nt][0] + bb2[nt][0], 0.f);
            float v1 = fmaxf(acc[mt][nt][1] + bb2[nt][1], 0.f);
            float v2 = fmaxf(acc[mt][nt][2] + bb2[nt][0], 0.f);
            float v3 = fmaxf(acc[mt][nt][3] + bb2[nt][1], 0.f);
            *(__nv_bfloat162*)&g_zb[(size_t)r0*LAT + cc]     = __floats2bfloat162_rn(v0, v1);
            *(__nv_bfloat162*)&g_zb[(size_t)(r0+8)*LAT + cc] = __floats2bfloat162_rn(v2, v3);
        }
    }
}

// ---------- candidate selection: conflict-free scans, fused collect ----------
__global__ void __launch_bounds__(256,1) k_cand(){
    __shared__ uint16_t keys[LAT];
    __shared__ int hist[256];
    __shared__ int misc[2];
    __shared__ int cnt, eqcnt;
    __shared__ int eqbuf[EQCAP];
    int row = blockIdx.x, t = threadIdx.x;

    const uint4* src = (const uint4*)(g_zb + (size_t)row*LAT);
    uint4* dk = (uint4*)keys;
    for (int i=t;i<LAT/8;i+=256) dk[i] = src[i];
    __syncthreads();

    const uint32_t* kw = (const uint32_t*)keys;   // 8192 words, 2 keys each
    int need = CAND;
    // pass 1: high byte (zeros skipped: output-neutral)
    hist[t]=0; __syncthreads();
    #pragma unroll 4
    for (int i=0;i<32;i++){
        uint32_t w2 = kw[t + 256*i];
        int k0 = w2 & 0xFFFF, k1 = (int)(w2 >> 16);
        if (k0) atomicAdd(&hist[k0>>8], 1);
        if (k1) atomicAdd(&hist[k1>>8], 1);
    }
    __syncthreads();
    if (t==0){
        int cum=0, b=255;
        for (; b>0; b--){ cum += hist[b]; if (cum>=need) break; }
        if (cum < need) cum += hist[0];
        misc[0]=b; misc[1]=need-(cum-hist[b]);
    }
    __syncthreads();
    int bhi = misc[0]; need = misc[1];
    __syncthreads();
    // pass 2: low byte within bucket
    hist[t]=0; __syncthreads();
    #pragma unroll 4
    for (int i=0;i<32;i++){
        uint32_t w2 = kw[t + 256*i];
        int k0 = w2 & 0xFFFF, k1 = (int)(w2 >> 16);
        if (k0 && (k0>>8)==bhi) atomicAdd(&hist[k0&255], 1);
        if (k1 && (k1>>8)==bhi) atomicAdd(&hist[k1&255], 1);
    }
    __syncthreads();
    if (t==0){
        int cum=0, b=255;
        for (; b>0; b--){ cum += hist[b]; if (cum>=need) break; }
        misc[0]=b; cnt=0; eqcnt=0;
    }
    __syncthreads();
    const int T = (bhi<<8) | misc[0];
    // fused collect: >T to global list, ==T staged to eqbuf
    #pragma unroll 4
    for (int i=0;i<32;i++){
        int wi = t + 256*i;
        uint32_t w2 = kw[wi];
        int k0 = w2 & 0xFFFF, k1 = (int)(w2 >> 16);
        if (k0 > T){
            int p = atomicAdd(&cnt,1);
            if (p < MAXC) g_cidx[(size_t)row*MAXC+p] = 2*wi;
        } else if (k0 == T && T > 0){
            int e = atomicAdd(&eqcnt,1);
            if (e < EQCAP) eqbuf[e] = 2*wi;
        }
        if (k1 > T){
            int p = atomicAdd(&cnt,1);
            if (p < MAXC) g_cidx[(size_t)row*MAXC+p] = 2*wi+1;
        } else if (k1 == T && T > 0){
            int e = atomicAdd(&eqcnt,1);
            if (e < EQCAP) eqbuf[e] = 2*wi+1;
        }
    }
    __syncthreads();
    int gt = (cnt < MAXC) ? cnt : MAXC;
    int ne = eqcnt; if (ne > EQCAP) ne = EQCAP;
    if (t < ne){
        int p = gt + t;
        if (p < MAXC) g_cidx[(size_t)row*MAXC+p] = eqbuf[t];
    }
    __syncthreads();
    if (t==0){
        int tot = gt + ne;
        g_ccnt[row] = (tot < MAXC) ? tot : MAXC;
    }
}

// ---------- exact fp32 recompute (2 candidates per warp) ----------
__global__ void __launch_bounds__(256,1) k_exact(const float* __restrict__ x,
                                                 const float* __restrict__ W,
                                                 const float* __restrict__ benc){
    __shared__ float4 xs[INDIM/4];
    __shared__ int cidx_s[MAXC];
    __shared__ int ccs;
    int row = blockIdx.x, t = threadIdx.x;
    xs[t] = ((const float4*)(x + (size_t)row*INDIM))[t];
    if (t < MAXC) cidx_s[t] = g_cidx[(size_t)row*MAXC+t];
    if (t == 0) ccs = g_ccnt[row];
    __syncthreads();
    int w = t>>5, lane = t&31;
    for (int p = 2*w; p < ccs; p += 16){
        int c1 = p+1;
        bool has1 = (c1 < ccs);
        int i0 = cidx_s[p];
        int i1 = has1 ? cidx_s[c1] : i0;
        const float4* w0 = (const float4*)(W + (size_t)i0*INDIM);
        const float4* w1 = (const float4*)(W + (size_t)i1*INDIM);
        float s0 = 0.f, s1 = 0.f;
        #pragma unroll
        for (int i=0;i<8;i++){
            float4 a = __ldg(&w0[lane + 32*i]);
            float4 b = __ldg(&w1[lane + 32*i]);
            float4 xv = xs[lane + 32*i];
            s0 = fmaf(a.x, xv.x, s0); s0 = fmaf(a.y, xv.y, s0);
            s0 = fmaf(a.z, xv.z, s0); s0 = fmaf(a.w, xv.w, s0);
            s1 = fmaf(b.x, xv.x, s1); s1 = fmaf(b.y, xv.y, s1);
            s1 = fmaf(b.z, xv.z, s1); s1 = fmaf(b.w, xv.w, s1);
        }
        #pragma unroll
        for (int o=16;o;o>>=1){
            s0 += __shfl_xor_sync(0xFFFFFFFFu, s0, o);
            s1 += __shfl_xor_sync(0xFFFFFFFFu, s1, o);
        }
        if (lane==0){
            g_cval[(size_t)row*MAXC+p] = fmaxf(s0 + __ldg(&benc[i0]), 0.f);
            if (has1) g_cval[(size_t)row*MAXC+c1] = fmaxf(s1 + __ldg(&benc[i1]), 0.f);
        }
    }
}

// ---------- fused zero + exact top-64 + full-row write ----------
__global__ void __launch_bounds__(256,1) k_selz(float* __restrict__ zout){
    extern __shared__ __align__(16) float rowbuf[];       // 16384 floats (64KB)
    __shared__ float v[MAXC];
    __shared__ int id[MAXC];
    __shared__ int ccs;
    int row = blockIdx.x, t = threadIdx.x;
    float4* rb4 = (float4*)rowbuf;
    #pragma unroll
    for (int i=t;i<LAT/4;i+=256) rb4[i] = make_float4(0.f,0.f,0.f,0.f);
    if (t==0) ccs = g_ccnt[row];
    if (t < TOPK){ g_aval[(size_t)row*TOPK+t] = 0.f; g_aidx[(size_t)row*TOPK+t] = 0; }
    __syncthreads();
    if (t < ccs){ v[t] = g_cval[(size_t)row*MAXC+t]; id[t] = g_cidx[(size_t)row*MAXC+t]; }
    __syncthreads();
    if (t < ccs){
        float vt = v[t]; int it = id[t];
        int r = 0;
        for (int j=0;j<ccs;j++)
            r += (v[j] > vt) || (v[j] == vt && id[j] < it);
        if (r < TOPK){
            g_aval[(size_t)row*TOPK+r] = vt;
            g_aidx[(size_t)row*TOPK+r] = it;
            rowbuf[it] = vt;
        }
    }
    __syncthreads();
    float4* dst = (float4*)(zout + (size_t)row*LAT);
    #pragma unroll
    for (int i=t;i<LAT/4;i+=256) dst[i] = rb4[i];
}

// ---------- sparse decode ----------
__global__ void __launch_bounds__(256,1) k_decode(const float* __restrict__ bdec,
                                                  float* __restrict__ recon){
    int row = blockIdx.x, t = threadIdx.x;
    __shared__ float sv[TOPK]; __shared__ int si[TOPK];
    if (t < TOPK){ sv[t]=g_aval[(size_t)row*TOPK+t]; si[t]=g_aidx[(size_t)row*TOPK+t]; }
    __syncthreads();
    float a0=bdec[t], a1=bdec[t+256], a2=bdec[t+512], a3=bdec[t+768];
    #pragma unroll 4
    for (int j=0;j<TOPK;j++){
        const float* wr = g_WdT + (size_t)si[j]*INDIM;
        float vv = sv[j];
        a0 = fmaf(vv, __ldg(wr+t),     a0);
        a1 = fmaf(vv, __ldg(wr+t+256), a1);
        a2 = fmaf(vv, __ldg(wr+t+512), a2);
        a3 = fmaf(vv, __ldg(wr+t+768), a3);
    }
    float* r = recon + (size_t)row*INDIM;
    r[t]=a0; r[t+256]=a1; r[t+512]=a2; r[t+768]=a3;
}

extern "C" void kernel_launch(void* const* d_in, const int* in_sizes, int n_in,
                              void* d_out, int out_size){
    const float* x    = (const float*)d_in[0];
    const float* Wenc = (const float*)d_in[1];
    const float* benc = (const float*)d_in[2];
    const float* Wdec = (const float*)d_in[3];
    const float* bdec = (const float*)d_in[4];
    float* out   = (float*)d_out;
    float* recon = out;
    float* zout  = out + (size_t)BATCH*INDIM;

    __nv_bfloat16 *xb, *wb;
    cudaGetSymbolAddress((void**)&xb, g_Xb);
    cudaGetSymbolAddress((void**)&wb, g_Wb);

    cudaFuncSetAttribute(k_gemm, cudaFuncAttributeMaxDynamicSharedMemorySize, SMEM_GEMM);
    cudaFuncSetAttribute(k_selz, cudaFuncAttributeMaxDynamicSharedMemorySize, 65536);

    int n4x = BATCH*INDIM/4, n4w = LAT*INDIM/4;
    // launch order: slot 4 (profiled) = k_gemm, same conditions as R12 measurement
    k_cvtx<<<(n4x+255)/256, 256>>>((const float4*)x, (__nv_bfloat162*)xb, n4x);
    k_cvtx<<<(n4w+255)/256, 256>>>((const float4*)Wenc, (__nv_bfloat162*)wb, n4w);
    k_transp<<<dim3(LAT/32, INDIM/32), dim3(32,8)>>>(Wdec);
    k_gemm<<<dim3(BATCH/GM, LAT/GN), 256, SMEM_GEMM>>>(benc);
    k_cand<<<BATCH, 256>>>();
    k_exact<<<BATCH, 256>>>(x, Wenc, benc);
    k_selz<<<BATCH, 256, 65536>>>(zout);
    k_decode<<<BATCH, 256>>>(bdec, recon);
}